// round 4
// baseline (speedup 1.0000x reference)
#include <cuda_runtime.h>
#include <cstdint>
#include <math.h>

// ---------------- scratch (device globals; no allocations) ----------------
__device__ float g_h1[131072000];   // 16*512*16000
__device__ float g_h2[32768000];    // 16*512*4000
__device__ float g_h3[16384000];    // 16*512*2000
__device__ float g_h4[8192000];     // 16*512*1000
__device__ float g_h5[4096000];     // 16*512*500
__device__ float g_zbn[4096000];    // [t*16+b][512]
__device__ float g_scale[5*512];
__device__ float g_shift[5*512];
__device__ float g_wt2[2097152];    // [(ci*8+k)*512 + co]
__device__ float g_wt345[3145728];  // [j][(ci*4+k)*512 + co]
__device__ float g_wiht[393216];    // [d*768 + j]
__device__ float g_gi[6144000];     // [(t*16+b)*768 + j]
__device__ float g_enc[98304];      // [(k*16+b)*512 + d]
__device__ float g_ct[4096];
__device__ float g_hlast[4096];
__device__ float g_pred[98304];     // [(k*16+c)*512 + d]
__device__ float g_total[3072];     // [(k*16+b)*16 + c]

// ---------------- weight transposes ----------------
__global__ void tr_w2_kernel(const float* __restrict__ w) {
    int id = blockIdx.x*256 + threadIdx.x;
    if (id >= 512*512*8) return;
    int co = id & 511;
    int r  = id >> 9;            // ci*8+k
    int ci = r >> 3, k = r & 7;
    g_wt2[id] = w[((long)co*512 + ci)*8 + k];
}
__global__ void tr_w345_kernel(const float* __restrict__ w) {
    int id = blockIdx.x*256 + threadIdx.x;
    if (id >= 3*512*512*4) return;
    int co = id & 511;
    int q  = id >> 9;
    int r  = q & 2047;           // ci*4+k
    int j  = q >> 11;
    int ci = r >> 2, k = r & 3;
    g_wt345[id] = w[(((long)j*512 + co)*512 + ci)*4 + k];
}
__global__ void tr_wih_kernel(const float* __restrict__ w) {
    int id = blockIdx.x*256 + threadIdx.x;
    if (id >= 512*768) return;
    int d = id / 768;
    int j = id - d*768;
    g_wiht[id] = w[(long)j*512 + d];
}

// ---------------- conv1: Cin=1, K=10, S=5, pad=3, T=16000 ----------------
__global__ void __launch_bounds__(256) conv1_kernel(
    const float* __restrict__ x, const float* __restrict__ w1, float* __restrict__ out)
{
    __shared__ float xs[656];
    __shared__ float ws[640];
    const int b = blockIdx.z, co0 = blockIdx.y*64, t0 = blockIdx.x*128;
    const int tid = threadIdx.x;
    const int base = 5*t0 - 3;
    const float* xb = x + (long)b*80000;
    for (int i = tid; i < 645; i += 256) {
        int p = base + i;
        xs[i] = (p >= 0 && p < 80000) ? xb[p] : 0.f;
    }
    for (int i = tid; i < 640; i += 256) ws[i] = w1[co0*10 + i];
    __syncthreads();
    for (int i = tid; i < 64*128; i += 256) {
        int co_l = i >> 7, t_l = i & 127;
        float a = 0.f;
        #pragma unroll
        for (int k = 0; k < 10; k++) a = fmaf(ws[co_l*10+k], xs[5*t_l+k], a);
        out[((long)b*512 + co0 + co_l)*16000 + t0 + t_l] = a;
    }
}

// ---------------- BN stats: one block per channel ----------------
__global__ void __launch_bounds__(256) stats_kernel(
    const float* __restrict__ h, int T, int l,
    const float* __restrict__ gamma, const float* __restrict__ beta)
{
    int c = blockIdx.x;
    int tid = threadIdx.x;
    float s = 0.f, s2 = 0.f;
    for (int b = 0; b < 16; b++) {
        const float* p = h + ((long)b*512 + c)*T;
        for (int i = tid; i < T; i += 256) { float v = p[i]; s += v; s2 = fmaf(v, v, s2); }
    }
    __shared__ double sh[256], sh2[256];
    sh[tid] = (double)s; sh2[tid] = (double)s2;
    __syncthreads();
    for (int st = 128; st > 0; st >>= 1) {
        if (tid < st) { sh[tid] += sh[tid+st]; sh2[tid] += sh2[tid+st]; }
        __syncthreads();
    }
    if (tid == 0) {
        double N = 16.0 * (double)T;
        double m = sh[0] / N;
        double var = sh2[0] / N - m*m;
        double sc = (double)gamma[l*512+c] / sqrt(var + 1e-5);
        g_scale[l*512+c] = (float)sc;
        g_shift[l*512+c] = (float)((double)beta[l*512+c] - m*sc);
    }
}

// ---------------- generic conv: Cin=512, BN+relu folded into input load ---
// tile: 128 co x 128 t per block; thread: 8 co x (2 groups x 4 consecutive t)
// static smem: ws[CI*K][128], xs[CI][S][132] (phase-deinterleaved input)
template<int K, int S, int CI>
__global__ void __launch_bounds__(256) convg_kernel(
    const float* __restrict__ in, const float* __restrict__ wt,
    const float* __restrict__ scale, const float* __restrict__ shift,
    float* __restrict__ out, int Tin, int Tout, int pad)
{
    constexpr int Q = K / S;           // 2 for both conv types
    constexpr int TW = 132;
    __shared__ float ws[CI*K*128];
    __shared__ float xs[CI*S*TW];
    const int b = blockIdx.z, co0 = blockIdx.y*128, t0 = blockIdx.x*128;
    const int tid = threadIdx.x;
    const int cog = tid >> 4;          // 0..15
    const int tx  = tid & 15;          // 0..15
    const int co_l = cog * 8;
    float acc[2][8][4];
    #pragma unroll
    for (int g = 0; g < 2; g++)
        #pragma unroll
        for (int i = 0; i < 8; i++)
            #pragma unroll
            for (int j = 0; j < 4; j++) acc[g][i][j] = 0.f;
    const long inb = (long)b*512*Tin;

    for (int cig = 0; cig < 512; cig += CI) {
        __syncthreads();
        for (int i = tid; i < CI*K*128; i += 256) {
            int row = i >> 7;          // local ci*K + k
            int co  = i & 127;
            ws[i] = wt[(long)(cig*K + row)*512 + co0 + co];
        }
        for (int i = tid; i < CI*S*TW; i += 256) {
            int ci = i / (S*TW);
            int u  = i - ci*(S*TW);
            int p  = S*t0 + u - pad;
            float v = 0.f;
            if (p >= 0 && p < Tin) {
                float raw = in[inb + (long)(cig+ci)*Tin + p];
                v = fmaxf(0.f, fmaf(raw, scale[cig+ci], shift[cig+ci]));
            }
            xs[ci*(S*TW) + (u % S)*TW + (u / S)] = v;
        }
        __syncthreads();
        #pragma unroll
        for (int ci = 0; ci < CI; ci++) {
            #pragma unroll
            for (int r = 0; r < S; r++) {
                float w0[Q][8];
                #pragma unroll
                for (int q = 0; q < Q; q++) {
                    int k = S*q + r;
                    const float4* wp = (const float4*)(ws + (ci*K + k)*128 + co_l);
                    float4 wa = wp[0], wb = wp[1];
                    w0[q][0]=wa.x; w0[q][1]=wa.y; w0[q][2]=wa.z; w0[q][3]=wa.w;
                    w0[q][4]=wb.x; w0[q][5]=wb.y; w0[q][6]=wb.z; w0[q][7]=wb.w;
                }
                #pragma unroll
                for (int g = 0; g < 2; g++) {
                    const float* xp = xs + ci*(S*TW) + r*TW + tx*4 + g*64;
                    float4 xa = *(const float4*)xp;
                    float xv[5];
                    xv[0]=xa.x; xv[1]=xa.y; xv[2]=xa.z; xv[3]=xa.w; xv[4]=xp[4];
                    #pragma unroll
                    for (int q = 0; q < Q; q++)
                        #pragma unroll
                        for (int i = 0; i < 8; i++)
                            #pragma unroll
                            for (int j = 0; j < 4; j++)
                                acc[g][i][j] = fmaf(w0[q][i], xv[j+q], acc[g][i][j]);
                }
            }
        }
    }
    #pragma unroll
    for (int g = 0; g < 2; g++) {
        int tb = t0 + tx*4 + g*64;
        if (tb < Tout) {
            #pragma unroll
            for (int i = 0; i < 8; i++) {
                float4 st;
                st.x = acc[g][i][0]; st.y = acc[g][i][1];
                st.z = acc[g][i][2]; st.w = acc[g][i][3];
                *(float4*)(out + ((long)b*512 + co0 + co_l + i)*Tout + tb) = st;
            }
        }
    }
}

// ---------------- zbn: BN5+relu, transpose to [t][b][d] ----------------
__global__ void zbn_kernel(const float* __restrict__ h5) {
    int t = blockIdx.x, b = blockIdx.y, d = threadIdx.x;  // 512 threads
    float raw = h5[((long)b*512 + d)*500 + t];
    float v = fmaxf(0.f, fmaf(raw, g_scale[4*512+d], g_shift[4*512+d]));
    g_zbn[((long)t*16 + b)*512 + d] = v;
}

__global__ void enc_kernel(const int* __restrict__ ts) {
    int k = blockIdx.x, b = blockIdx.y, d = threadIdx.x;
    int t = ts[b] + k + 1;
    g_enc[((long)(k*16) + b)*512 + d] = g_zbn[((long)t*16 + b)*512 + d];
}

// ---------------- gi GEMM: [8000 x 512] @ [512 x 768] + bih ----------------
__global__ void __launch_bounds__(256) gi_kernel(const float* __restrict__ bih) {
    __shared__ float as[128*17];
    __shared__ float bs[16*64];
    const int r0 = blockIdx.x*128, c0 = blockIdx.y*64;
    const int tid = threadIdx.x;
    const int cx = tid & 15;   // col group (4 cols)
    const int ry = tid >> 4;   // 0..15
    float acc[8][4];
    #pragma unroll
    for (int i = 0; i < 8; i++)
        #pragma unroll
        for (int j = 0; j < 4; j++) acc[i][j] = 0.f;
    for (int d0 = 0; d0 < 512; d0 += 16) {
        __syncthreads();
        for (int i = tid; i < 2048; i += 256) {
            int row = i >> 4, dd = i & 15;
            int rg = r0 + row;
            as[row*17 + dd] = (rg < 8000) ? g_zbn[(long)rg*512 + d0 + dd] : 0.f;
        }
        for (int i = tid; i < 1024; i += 256) {
            int dd = i >> 6, col = i & 63;
            bs[i] = g_wiht[(long)(d0+dd)*768 + c0 + col];
        }
        __syncthreads();
        #pragma unroll
        for (int dd = 0; dd < 16; dd++) {
            float4 b4 = *(const float4*)(bs + dd*64 + cx*4);
            float bv[4] = {b4.x, b4.y, b4.z, b4.w};
            #pragma unroll
            for (int ii = 0; ii < 8; ii++) {
                float av = as[(ry + 16*ii)*17 + dd];
                #pragma unroll
                for (int j = 0; j < 4; j++) acc[ii][j] = fmaf(av, bv[j], acc[ii][j]);
            }
        }
    }
    #pragma unroll
    for (int ii = 0; ii < 8; ii++) {
        int rg = r0 + ry + 16*ii;
        if (rg < 8000) {
            #pragma unroll
            for (int j = 0; j < 4; j++)
                g_gi[(long)rg*768 + c0 + cx*4 + j] = acc[ii][j] + bih[c0 + cx*4 + j];
        }
    }
}

// ---------------- GRU: persistent, 1 block per batch ----------------
// warp w handles rows [w*96, w*96+96). lane = g*8+l: group g of 8 lanes per
// row; lane caches h[l*32 .. l*32+31] in regs; 3-stage width-8 shuffle.
__global__ void __launch_bounds__(256) gru_kernel(
    const float* __restrict__ hidden, const int* __restrict__ ts,
    const float* __restrict__ whh, const float* __restrict__ bhh,
    const float* __restrict__ bih)
{
    const int b = blockIdx.x;
    const int tid = threadIdx.x;
    const int w = tid >> 5, lane = tid & 31;
    const int g = lane >> 3, l = lane & 7;
    __shared__ float h_s[256];
    __shared__ float gh_s[768];
    h_s[tid] = hidden[b*256 + tid];
    const int tsb = ts[b];
    for (int t = 0; t < 500; t++) {
        __syncthreads();
        float hv[32];
        #pragma unroll
        for (int i = 0; i < 8; i++) {
            float4 h4 = *(const float4*)(h_s + l*32 + i*4);
            hv[i*4+0]=h4.x; hv[i*4+1]=h4.y; hv[i*4+2]=h4.z; hv[i*4+3]=h4.w;
        }
        #pragma unroll 4
        for (int it = 0; it < 24; it++) {
            int row = w*96 + it*4 + g;
            const float4* wp = (const float4*)(whh + (long)row*256 + l*32);
            float a = 0.f;
            #pragma unroll
            for (int i = 0; i < 8; i++) {
                float4 w4 = wp[i];
                a = fmaf(w4.x, hv[i*4+0], a);
                a = fmaf(w4.y, hv[i*4+1], a);
                a = fmaf(w4.z, hv[i*4+2], a);
                a = fmaf(w4.w, hv[i*4+3], a);
            }
            a += __shfl_down_sync(0xffffffffu, a, 4, 8);
            a += __shfl_down_sync(0xffffffffu, a, 2, 8);
            a += __shfl_down_sync(0xffffffffu, a, 1, 8);
            if (l == 0) gh_s[row] = a + bhh[row];
        }
        __syncthreads();
        bool masked = (t > tsb);
        const float* gp = g_gi + ((long)t*16 + b)*768;
        float gr = masked ? bih[tid]     : gp[tid];
        float gz = masked ? bih[256+tid] : gp[256+tid];
        float gn = masked ? bih[512+tid] : gp[512+tid];
        float r = 1.f/(1.f + expf(-(gr + gh_s[tid])));
        float z = 1.f/(1.f + expf(-(gz + gh_s[256+tid])));
        float n = tanhf(gn + r*gh_s[512+tid]);
        float hn = (1.f - z)*n + z*h_s[tid];
        h_s[tid] = hn;
        if (t == tsb) g_ct[b*256+tid] = hn;
        if (t == 499) g_hlast[b*256+tid] = hn;
    }
}

// ---------------- pred: [16x256] x Wk_w[k][512][256] ----------------
__global__ void __launch_bounds__(128) pred_kernel(
    const float* __restrict__ wkw, const float* __restrict__ wkb)
{
    const int k = blockIdx.x, d0 = blockIdx.y*128;
    const int tid = threadIdx.x;
    __shared__ float ct_s[16*256];
    __shared__ float wt_s[128*33];
    for (int i = tid; i < 4096; i += 128) ct_s[i] = g_ct[i];
    float acc[16];
    #pragma unroll
    for (int bb = 0; bb < 16; bb++) acc[bb] = 0.f;
    for (int h0 = 0; h0 < 256; h0 += 32) {
        __syncthreads();
        for (int i = tid; i < 4096; i += 128) {
            int row = i >> 5, hh = i & 31;
            wt_s[row*33 + hh] = wkw[((long)k*512 + d0 + row)*256 + h0 + hh];
        }
        __syncthreads();
        #pragma unroll
        for (int hh = 0; hh < 32; hh++) {
            float wv = wt_s[tid*33 + hh];
            #pragma unroll
            for (int bb = 0; bb < 16; bb++)
                acc[bb] = fmaf(wv, ct_s[bb*256 + h0 + hh], acc[bb]);
        }
    }
    for (int bb = 0; bb < 16; bb++)
        g_pred[((long)(k*16) + bb)*512 + d0 + tid] = acc[bb] + wkb[k*512 + d0 + tid];
}

// ---------------- total[k][b][c] = enc[k][b] . pred[k][c] ----------------
__global__ void __launch_bounds__(256) total_kernel() {
    const int k = blockIdx.x, tid = threadIdx.x;
    const int b = tid >> 4, c = tid & 15;
    const float* ep = g_enc + ((long)(k*16) + b)*512;
    const float* pp = g_pred + ((long)(k*16) + c)*512;
    float a = 0.f;
    for (int d = 0; d < 512; d++) a = fmaf(ep[d], pp[d], a);
    g_total[(k*16+b)*16 + c] = a;
}

// ---------------- final: nce, accuracy, copy h_last ----------------
__global__ void final_kernel(float* __restrict__ out) {
    const int tid = threadIdx.x;
    for (int i = tid; i < 4096; i += 256) out[2+i] = g_hlast[i];
    if (tid == 0) {
        double nce = 0.0;
        for (int k = 0; k < 12; k++) {
            for (int b = 0; b < 16; b++) {
                const float* row = g_total + (k*16+b)*16;
                float m = row[0];
                for (int c = 1; c < 16; c++) m = fmaxf(m, row[c]);
                double s = 0.0;
                for (int c = 0; c < 16; c++) s += exp((double)row[c] - (double)m);
                double lse = (double)m + log(s);
                nce += (double)row[b] - lse;
            }
        }
        out[1] = (float)(nce / (-16.0 * 12.0));
        double lseb[16];
        for (int b = 0; b < 16; b++) {
            const float* row = g_total + (11*16+b)*16;
            float m = row[0];
            for (int c = 1; c < 16; c++) m = fmaxf(m, row[c]);
            double s = 0.0;
            for (int c = 0; c < 16; c++) s += exp((double)row[c] - (double)m);
            lseb[b] = (double)m + log(s);
        }
        int correct = 0;
        for (int c = 0; c < 16; c++) {
            double best = -1e300; int bb = -1;
            for (int b = 0; b < 16; b++) {
                double v = (double)g_total[(11*16+b)*16 + c] - lseb[b];
                if (v > best) { best = v; bb = b; }
            }
            if (bb == c) correct++;
        }
        out[0] = (float)correct / 16.0f;
    }
}

// ---------------- host ----------------
extern "C" void kernel_launch(void* const* d_in, const int* in_sizes, int n_in,
                              void* d_out, int out_size) {
    const float* x      = (const float*)d_in[0];
    const float* hidden = (const float*)d_in[1];
    const int*   ts     = (const int*)  d_in[3];
    const float* w1     = (const float*)d_in[4];
    const float* w2     = (const float*)d_in[5];
    const float* w345   = (const float*)d_in[6];
    const float* gamma  = (const float*)d_in[7];
    const float* beta   = (const float*)d_in[8];
    const float* wih    = (const float*)d_in[9];
    const float* whh    = (const float*)d_in[10];
    const float* bih    = (const float*)d_in[11];
    const float* bhh    = (const float*)d_in[12];
    const float* wkw    = (const float*)d_in[13];
    const float* wkb    = (const float*)d_in[14];
    float* out = (float*)d_out;

    float *h1, *h2, *h3, *h4, *h5, *wt2, *wt345, *sc, *sh;
    cudaGetSymbolAddress((void**)&h1, g_h1);
    cudaGetSymbolAddress((void**)&h2, g_h2);
    cudaGetSymbolAddress((void**)&h3, g_h3);
    cudaGetSymbolAddress((void**)&h4, g_h4);
    cudaGetSymbolAddress((void**)&h5, g_h5);
    cudaGetSymbolAddress((void**)&wt2, g_wt2);
    cudaGetSymbolAddress((void**)&wt345, g_wt345);
    cudaGetSymbolAddress((void**)&sc, g_scale);
    cudaGetSymbolAddress((void**)&sh, g_shift);

    tr_w2_kernel<<<8192, 256>>>(w2);
    tr_w345_kernel<<<12288, 256>>>(w345);
    tr_wih_kernel<<<1536, 256>>>(wih);

    conv1_kernel<<<dim3(125, 8, 16), 256>>>(x, w1, h1);
    stats_kernel<<<512, 256>>>(h1, 16000, 0, gamma, beta);

    convg_kernel<8,4,4><<<dim3(32, 4, 16), 256>>>(h1, wt2, sc + 0*512, sh + 0*512, h2, 16000, 4000, 2);
    stats_kernel<<<512, 256>>>(h2, 4000, 1, gamma, beta);

    convg_kernel<4,2,8><<<dim3(16, 4, 16), 256>>>(h2, wt345 + 0*1048576, sc + 1*512, sh + 1*512, h3, 4000, 2000, 1);
    stats_kernel<<<512, 256>>>(h3, 2000, 2, gamma, beta);

    convg_kernel<4,2,8><<<dim3(8, 4, 16), 256>>>(h3, wt345 + 1*1048576, sc + 2*512, sh + 2*512, h4, 2000, 1000, 1);
    stats_kernel<<<512, 256>>>(h4, 1000, 3, gamma, beta);

    convg_kernel<4,2,8><<<dim3(4, 4, 16), 256>>>(h4, wt345 + 2*1048576, sc + 3*512, sh + 3*512, h5, 1000, 500, 1);
    stats_kernel<<<512, 256>>>(h5, 500, 4, gamma, beta);

    zbn_kernel<<<dim3(500, 16), 512>>>(h5);
    enc_kernel<<<dim3(12, 16), 512>>>(ts);
    gi_kernel<<<dim3(63, 12), 256>>>(bih);
    gru_kernel<<<16, 256>>>(hidden, ts, whh, bhh, bih);
    pred_kernel<<<dim3(12, 4), 128>>>(wkw, wkb);
    total_kernel<<<12, 256>>>();
    final_kernel<<<1, 256>>>(out);
}